// round 15
// baseline (speedup 1.0000x reference)
#include <cuda_runtime.h>
#include <cuda_fp16.h>
#include <cstdint>

#define NN 1024
#define DD 64
#define NE 16384
#define NP 8192
#define LNEPS 1e-5f

// ------------------------- helpers ------------------------------------------
__device__ __forceinline__ uint32_t pack_h2(float x, float y) {
    __half2 h = __floats2half2_rn(x, y);
    return *reinterpret_cast<uint32_t*>(&h);
}
__device__ __forceinline__ uint32_t hmul2u(uint32_t a, uint32_t b) {
    uint32_t r; asm("mul.rn.f16x2 %0,%1,%2;" : "=r"(r) : "r"(a), "r"(b)); return r;
}
__device__ __forceinline__ uint32_t hadd2u(uint32_t a, uint32_t b) {
    uint32_t r; asm("add.rn.f16x2 %0,%1,%2;" : "=r"(r) : "r"(a), "r"(b)); return r;
}
__device__ __forceinline__ float2 h22f2(uint32_t h) {
    __half2 hh = *reinterpret_cast<__half2*>(&h);
    return __half22float2(hh);
}
__device__ __forceinline__ void mma_f16(float* d, uint32_t a0, uint32_t a1,
                                        uint32_t a2, uint32_t a3,
                                        uint32_t b0, uint32_t b1) {
    asm volatile(
        "mma.sync.aligned.m16n8k16.row.col.f32.f16.f16.f32 "
        "{%0,%1,%2,%3}, {%4,%5,%6,%7}, {%8,%9}, {%0,%1,%2,%3};"
        : "+f"(d[0]), "+f"(d[1]), "+f"(d[2]), "+f"(d[3])
        : "r"(a0), "r"(a1), "r"(a2), "r"(a3), "r"(b0), "r"(b1));
}
__device__ __forceinline__ void red2(float* gptr, float x, float y) {
    asm volatile("red.global.add.v2.f32 [%0], {%1,%2};"
                 :: "l"(gptr), "f"(x), "f"(y) : "memory");
}

// ------------------------- scratch (device globals) -------------------------
__device__ float    d_h[NN*DD];
__device__ float    d_hn[NN*DD];
__device__ float    d_aggr[NN*DD];
__device__ float    d_deg[NN];
__device__ unsigned d_bitmap[NN*NN/32];
__device__ float    d_vecp[NN*DD];
__device__ float    d_vecq[NN*DD];
__device__ float    d_VP[NN*DD];
__device__ float    d_VQ[NN*DD];

// ------------------------- phase A ------------------------------------------
__global__ void k_init(const int* __restrict__ x, const float* __restrict__ emb) {
    int t  = blockIdx.x*blockDim.x + threadIdx.x;
    int st = gridDim.x*blockDim.x;
    for (int i=t; i<NN*NN/32; i+=st) d_bitmap[i] = 0u;
    for (int i=t; i<NN;       i+=st) d_deg[i]    = 0.f;
    for (int i=t; i<NN*DD;    i+=st) {
        d_vecp[i]=0.f; d_vecq[i]=0.f; d_aggr[i]=0.f;
        d_h[i] = emb[x[i>>6]*DD + (i&63)];
    }
}

__global__ void k_scat0(const int* __restrict__ ei) {
    int t = blockIdx.x*blockDim.x + threadIdx.x;
    if (t < NE*32) {
        int e = t>>5, cq = t&31;
        int s = ei[e], d = ei[NE+e];
        float2 v = *reinterpret_cast<const float2*>(&d_h[s*DD + cq*2]);
        red2(&d_aggr[d*DD + cq*2], v.x, v.y);
        if (cq == 0) {
            atomicAdd(&d_deg[d], 1.f);
            unsigned idx = (unsigned)s*NN + (unsigned)d;
            atomicOr(&d_bitmap[idx>>5], 1u << (idx & 31u));
        }
    }
}

__global__ void k_scatter(const int* __restrict__ ei) {
    int t = blockIdx.x*blockDim.x + threadIdx.x;
    if (t < NE*32) {
        int e = t>>5, cq = t&31;
        float2 v = *reinterpret_cast<const float2*>(&d_hn[ei[e]*DD + cq*2]);
        red2(&d_aggr[ei[NE+e]*DD + cq*2], v.x, v.y);
    }
}

__global__ void k_sage(const float* __restrict__ Wl, const float* __restrict__ bl,
                       const float* __restrict__ Wr, int layer) {
    __shared__ float s_in[DD], s_ag[DD], s_red[DD];
    int i = blockIdx.x, c = threadIdx.x;
    const float* hs = layer ? d_hn : d_h;
    float*       hd = layer ? d_h  : d_hn;
    float dg = fmaxf(d_deg[i], 1.f);
    s_in[c] = hs[i*DD+c];
    s_ag[c] = d_aggr[i*DD+c] / dg;
    d_aggr[i*DD+c] = 0.f;
    __syncthreads();
    const float* wl = Wl + layer*DD*DD;
    const float* wr = Wr + layer*DD*DD;
    float acc = bl[layer*DD + c];
    #pragma unroll 8
    for (int k=0; k<DD; k++)
        acc = fmaf(s_ag[k], wl[k*DD+c], fmaf(s_in[k], wr[k*DD+c], acc));
    s_red[c] = acc;
    __syncthreads();
    float m = 0.f;
    #pragma unroll 8
    for (int k=0; k<DD; k++) m += s_red[k];
    m *= (1.f/DD);
    float v = 0.f;
    #pragma unroll 8
    for (int k=0; k<DD; k++) { float dd0 = s_red[k]-m; v = fmaf(dd0, dd0, v); }
    v *= (1.f/DD);
    hd[i*DD+c] = (acc - m) * rsqrtf(v + LNEPS);
}

// ------------------------- phase B: mma.sync f16 pair kernel ----------------
// 2 CTAs per triangular tile (split by i-half): 32 i-rows x 64 jj per CTA.
struct PairSmem {
    uint32_t hi_h[32][36];     //  4608 B
    uint32_t hj_h[64][36];     //  9216 B
    uint32_t swh[32][68];      //  8704 B
    uint32_t st_h[8][16][34];  // 17408 B : warp row sums (half2, write-once/i0b)
    uint32_t st2_h[8][16][34]; // 17408 B : warp mirror corrections (half2 RMW)
    float    vqa[64][68];      // 17408 B
    float    vqa2[64][68];     // 17408 B
    float    svp[32][68];      //  8704 B
    float    svq2[32][68];     //  8704 B
    float    hwe[64], hbias[64];
    unsigned bm0[32][2];
    unsigned bm1[64];
};

__device__ __forceinline__ int wd2ch(int wd) { return ((wd>>2)<<3) | ((wd&3)<<1); }

__device__ __forceinline__ void ln16s(const float* pre, float& m, float& r) {
    float s1 = 0.f, s2 = 0.f;
    #pragma unroll
    for (int i=0;i<16;i++) { s1 += pre[i]; s2 = fmaf(pre[i], pre[i], s2); }
    s1 += __shfl_xor_sync(0xffffffffu, s1, 1);
    s2 += __shfl_xor_sync(0xffffffffu, s2, 1);
    s1 += __shfl_xor_sync(0xffffffffu, s1, 2);
    s2 += __shfl_xor_sync(0xffffffffu, s2, 2);
    m = s1 * (1.f/DD);
    r = rsqrtf(fmaf(-m, m, s2*(1.f/DD)) + LNEPS);
}

__device__ __forceinline__ void vq_reduce_acc(const float* vs, float* vqrow,
                                              int g, int tg) {
    uint32_t vh[8];
    #pragma unroll
    for (int i=0;i<8;i++) vh[i] = pack_h2(vs[2*i], vs[2*i+1]);
    #pragma unroll
    for (int msk=4; msk<=16; msk<<=1) {
        #pragma unroll
        for (int i=0;i<8;i++)
            vh[i] = hadd2u(vh[i], __shfl_xor_sync(0xffffffffu, vh[i], msk));
    }
    if (g == 0) {
        #pragma unroll
        for (int nt=0; nt<8; nt++) {
            int ch0 = nt*8 + 2*tg;
            float2 add = h22f2(vh[nt]);
            float2* p = reinterpret_cast<float2*>(&vqrow[ch0]);
            float2 v = *p; v.x += add.x; v.y += add.y; *p = v;
        }
    }
}

__device__ __forceinline__ void emit(float* rs, float* vqrow,
                                     const float* pre0, const float* pre1,
                                     int g, int tg,
                                     float& m0, float& r0, float& m1, float& r1) {
    ln16s(pre0, m0, r0);
    ln16s(pre1, m1, r1);
    float vs[16];
    #pragma unroll
    for (int nt=0; nt<8; nt++) {
        int i0i = 2*nt, i1i = i0i+1;
        float b00 = fmaxf((pre0[i0i]-m0)*r0, 0.f);
        float b01 = fmaxf((pre0[i1i]-m0)*r0, 0.f);
        float b10 = fmaxf((pre1[i0i]-m1)*r1, 0.f);
        float b11 = fmaxf((pre1[i1i]-m1)*r1, 0.f);
        vs[i0i] = b00 + b10; vs[i1i] = b01 + b11;
        rs[i0i]    += b00;  rs[i1i]    += b01;
        rs[16+i0i] += b10;  rs[16+i1i] += b11;
    }
    vq_reduce_acc(vs, vqrow, g, tg);
}

__device__ __forceinline__ void emit_delta(uint32_t (*stacc)[34], float* vqrow,
                                           const float* pre0, const float* pre1,
                                           float d0, float d1,
                                           float m0, float r0, float m1, float r1,
                                           const float* we_r, int g, int tg) {
    float pm0[16], pm1[16];
    #pragma unroll
    for (int i=0;i<16;i++) {
        pm0[i] = fmaf(d0, we_r[i], pre0[i]);
        pm1[i] = fmaf(d1, we_r[i], pre1[i]);
    }
    float mm0, rr0, mm1, rr1;
    ln16s(pm0, mm0, rr0);
    ln16s(pm1, mm1, rr1);
    float vs[16];
    #pragma unroll
    for (int nt=0; nt<8; nt++) {
        int i0i = 2*nt, i1i = i0i+1;
        float dl00 = fmaxf((pm0[i0i]-mm0)*rr0,0.f) - fmaxf((pre0[i0i]-m0)*r0,0.f);
        float dl01 = fmaxf((pm0[i1i]-mm0)*rr0,0.f) - fmaxf((pre0[i1i]-m0)*r0,0.f);
        float dl10 = fmaxf((pm1[i0i]-mm1)*rr1,0.f) - fmaxf((pre1[i0i]-m1)*r1,0.f);
        float dl11 = fmaxf((pm1[i1i]-mm1)*rr1,0.f) - fmaxf((pre1[i1i]-m1)*r1,0.f);
        vs[i0i] = dl00 + dl10; vs[i1i] = dl01 + dl11;
        int wd = nt*4 + tg;
        stacc[g  ][wd] = hadd2u(stacc[g  ][wd], pack_h2(dl00, dl01));
        stacc[g+8][wd] = hadd2u(stacc[g+8][wd], pack_h2(dl10, dl11));
    }
    vq_reduce_acc(vs, vqrow, g, tg);
}

__global__ void __launch_bounds__(256,2) k_pair(const float* __restrict__ hW,
                                                const float* __restrict__ hb) {
    extern __shared__ char smraw[];
    PairSmem* sm = reinterpret_cast<PairSmem*>(smraw);
    int t = threadIdx.x;
    int lane = t & 31, w = t >> 5;
    int g = lane >> 2, tg = lane & 3;

    int tile = blockIdx.x >> 1, ihalf = blockIdx.x & 1;
    int bi = 0, rem = tile;
    while (rem >= 16 - bi) { rem -= 16 - bi; bi++; }
    int bj = bi + rem;
    int gi0 = bi*64 + ihalf*32, j0 = bj*64;
    bool diag = (bi == bj);

    // ---- stage ----
    for (int idx=t; idx<2048; idx+=256) {
        int r = idx>>5, kp = idx&31;
        sm->hj_h[r][kp] = pack_h2(d_h[(j0+r)*DD + 2*kp], d_h[(j0+r)*DD + 2*kp+1]);
        sm->swh[kp][r]  = pack_h2(hW[(2*kp)*DD + r], hW[(2*kp+1)*DD + r]);
    }
    for (int idx=t; idx<1024; idx+=256) {
        int r = idx>>5, kp = idx&31;
        sm->hi_h[r][kp] = pack_h2(d_h[(gi0+r)*DD + 2*kp], d_h[(gi0+r)*DD + 2*kp+1]);
    }
    for (int idx=t; idx<64*68; idx+=256) {
        reinterpret_cast<float*>(sm->vqa )[idx] = 0.f;
        reinterpret_cast<float*>(sm->vqa2)[idx] = 0.f;
    }
    for (int idx=t; idx<32*68; idx+=256) {
        reinterpret_cast<float*>(sm->svp )[idx] = 0.f;
        reinterpret_cast<float*>(sm->svq2)[idx] = 0.f;
    }
    if (t < DD) { sm->hwe[t] = hW[DD*DD + t]; sm->hbias[t] = hb[t]; }
    if (t >= 64 && t < 128) {
        int r = (t-64)>>1, wd = t&1;
        sm->bm0[r][wd] = d_bitmap[((unsigned)(gi0+r)*NN + (unsigned)j0)/32 + wd];
    } else if (t >= 128 && t < 192) {
        int r = t-128;
        sm->bm1[r] = d_bitmap[((unsigned)(j0+r)*NN + (unsigned)gi0)/32];
    }
    __syncthreads();

    float hb_r[16], we_r[16];
    #pragma unroll
    for (int i=0;i<16;i++) {
        int ch = (i>>1)*8 + 2*tg + (i&1);
        hb_r[i] = sm->hbias[ch];
        we_r[i] = sm->hwe[ch];
    }

    for (int i0b=0; i0b<2; i0b++) {
        int ii0 = i0b*16;
        {
            uint2 z = make_uint2(0u,0u);
            uint32_t* st2f = &sm->st2_h[w][0][0];
            for (int idx=lane; idx<16*17; idx+=32)
                *reinterpret_cast<uint2*>(st2f + idx*2) = z;
        }
        float rs[32];
        #pragma unroll
        for (int i=0;i<32;i++) rs[i] = 0.f;
        __syncwarp();

        // single-jj loop: 8 iterations, one acc set live at a time
        for (int q=0; q<8; q++) {
            int jj = w*8 + q;

            float acc[8][4];
            #pragma unroll
            for (int nt=0; nt<8; nt++)
                acc[nt][0]=acc[nt][1]=acc[nt][2]=acc[nt][3]=0.f;

            #pragma unroll
            for (int kt=0; kt<4; kt++) {
                int kp0 = kt*8 + tg, kp1 = kp0 + 4;
                uint32_t hj0 = sm->hj_h[jj][kp0], hj1 = sm->hj_h[jj][kp1];
                uint32_t hg0 = sm->hi_h[ii0+g][kp0],   hg1 = sm->hi_h[ii0+g][kp1];
                uint32_t h80 = sm->hi_h[ii0+g+8][kp0], h81 = sm->hi_h[ii0+g+8][kp1];
                uint32_t a0 = hmul2u(hg0, hj0);
                uint32_t a1 = hmul2u(h80, hj0);
                uint32_t a2 = hmul2u(hg1, hj1);
                uint32_t a3 = hmul2u(h81, hj1);
                #pragma unroll
                for (int nt=0; nt<8; nt++) {
                    uint32_t b0 = sm->swh[kp0][nt*8 + g];
                    uint32_t b1 = sm->swh[kp1][nt*8 + g];
                    mma_f16(acc[nt], a0, a1, a2, a3, b0, b1);
                }
            }

            float e_g  = ((sm->bm0[ii0+g  ][jj>>5] >> (jj&31)) & 1u) ? 1.f : 0.f;
            float e_g8 = ((sm->bm0[ii0+g+8][jj>>5] >> (jj&31)) & 1u) ? 1.f : 0.f;
            float pre0[16], pre1[16];
            #pragma unroll
            for (int nt=0; nt<8; nt++) {
                #pragma unroll
                for (int hf=0; hf<2; hf++) {
                    int i = 2*nt + hf;
                    pre0[i] = acc[nt][hf]   + hb_r[i] + e_g *we_r[i];
                    pre1[i] = acc[nt][2+hf] + hb_r[i] + e_g8*we_r[i];
                }
            }
            float m0, r0, m1, r1;
            emit(rs, sm->vqa[jj], pre0, pre1, g, tg, m0, r0, m1, r1);

            if (!diag) {
                float ep_g  = ((sm->bm1[jj] >> ((ii0+g  )&31)) & 1u) ? 1.f : 0.f;
                float ep_g8 = ((sm->bm1[jj] >> ((ii0+g+8)&31)) & 1u) ? 1.f : 0.f;
                float dd0 = ep_g - e_g, dd1 = ep_g8 - e_g8;
                bool nd = (dd0 != 0.f) || (dd1 != 0.f);
                if (__any_sync(0xffffffffu, nd)) {
                    emit_delta(sm->st2_h[w], sm->vqa2[jj], pre0, pre1,
                               dd0, dd1, m0, r0, m1, r1, we_r, g, tg);
                }
            }
        }

        // ---- write register row sums to st_h (half2, once per i0b) ----
        #pragma unroll
        for (int nt=0; nt<8; nt++) {
            int wd = nt*4 + tg;
            sm->st_h[w][g  ][wd] = pack_h2(rs[2*nt],    rs[2*nt+1]);
            sm->st_h[w][g+8][wd] = pack_h2(rs[16+2*nt], rs[16+2*nt+1]);
        }

        // ---- block reduce (once per i0b) ----
        __syncthreads();
        {
            int r = t >> 4, wbase = (t & 15)*2;
            #pragma unroll
            for (int u=0; u<2; u++) {
                int wd = wbase + u;
                float sx = 0.f, sy = 0.f;
                #pragma unroll
                for (int ww=0; ww<8; ww++) {
                    float2 v = h22f2(sm->st_h[ww][r][wd]);
                    sx += v.x; sy += v.y;
                }
                int ch = wd2ch(wd);
                sm->svp[ii0+r][ch]   += sx;
                sm->svp[ii0+r][ch+1] += sy;
                if (!diag) {
                    float tx = 0.f, ty = 0.f;
                    #pragma unroll
                    for (int ww=0; ww<8; ww++) {
                        float2 v = h22f2(sm->st2_h[ww][r][wd]);
                        tx += v.x; ty += v.y;
                    }
                    sm->svq2[ii0+r][ch]   += tx;
                    sm->svq2[ii0+r][ch+1] += ty;
                }
            }
        }
        __syncthreads();
    }

    // ---- flush ----
    for (int idx=t; idx<1024; idx+=256) {
        int rr = idx>>5, cq = (idx&31)*2;
        float rs0 = sm->svp[rr][cq], rs1 = sm->svp[rr][cq+1];
        red2(&d_vecp[(gi0+rr)*DD + cq], rs0, rs1);
        if (!diag)
            red2(&d_vecq[(gi0+rr)*DD + cq], rs0 + sm->svq2[rr][cq], rs1 + sm->svq2[rr][cq+1]);
    }
    for (int idx=t; idx<2048; idx+=256) {
        int rr = idx>>5, cq = (idx&31)*2;
        float cs0 = sm->vqa[rr][cq], cs1 = sm->vqa[rr][cq+1];
        red2(&d_vecq[(j0+rr)*DD + cq], cs0, cs1);
        if (!diag)
            red2(&d_vecp[(j0+rr)*DD + cq], cs0 + sm->vqa2[rr][cq], cs1 + sm->vqa2[rr][cq+1]);
    }
}

// ------------------------- phase C ------------------------------------------
__global__ void k_prec(const float* __restrict__ gW) {
    __shared__ float s_v[DD];
    int i = blockIdx.x, c = threadIdx.x;
    int which = blockIdx.y;
    const float* src = which ? d_vecq : d_vecp;
    const float* w   = gW + (which ? 129 : 65)*DD;
    float*       dst = which ? d_VQ : d_VP;
    s_v[c] = src[i*DD + c];
    __syncthreads();
    float acc = 0.f;
    #pragma unroll 8
    for (int k=0; k<DD; k++) acc = fmaf(s_v[k], w[k*DD+c], acc);
    dst[i*DD + c] = acc;
}

__global__ void k_gpairs(const int* __restrict__ pos, const float* __restrict__ gW,
                         const float* __restrict__ gb, const float* __restrict__ lW,
                         const float* __restrict__ lb, float* __restrict__ out) {
    __shared__ float sgw[DD+1][DD];
    __shared__ float sgb[DD], slw[DD];
    int t = threadIdx.x;
    for (int idx=t; idx<(DD+1)*DD; idx+=256) sgw[idx>>6][idx&63] = gW[idx];
    if (t < DD) { sgb[t] = gb[t]; slw[t] = lW[t]; }
    __syncthreads();

    int gt = blockIdx.x*256 + t;
    int p = gt >> 5, lane = gt & 31;
    if (p >= NP) return;
    int i = pos[2*p], j = pos[2*p+1];
    int c0 = lane, c1 = lane + 32;
    const float* hi = d_h + i*DD;
    const float* hj = d_h + j*DD;

    float g0 = 0.f, g1 = 0.f;
    #pragma unroll 8
    for (int k=0; k<DD; k++) {
        float a = hi[k]*hj[k];
        g0 = fmaf(a, sgw[k][c0], g0);
        g1 = fmaf(a, sgw[k][c1], g1);
    }
    unsigned bij = (unsigned)i*NN + (unsigned)j;
    unsigned bji = (unsigned)j*NN + (unsigned)i;
    float eij = ((d_bitmap[bij>>5] >> (bij & 31u)) & 1u) ? 1.f : 0.f;
    float eji = ((d_bitmap[bji>>5] >> (bji & 31u)) & 1u) ? 1.f : 0.f;

    float aA0 = g0 + sgb[c0] + d_VP[i*DD+c0] + d_VQ[j*DD+c0] + eij*sgw[DD][c0];
    float aA1 = g1 + sgb[c1] + d_VP[i*DD+c1] + d_VQ[j*DD+c1] + eij*sgw[DD][c1];
    float aB0 = g0 + sgb[c0] + d_VP[j*DD+c0] + d_VQ[i*DD+c0] + eji*sgw[DD][c0];
    float aB1 = g1 + sgb[c1] + d_VP[j*DD+c1] + d_VQ[i*DD+c1] + eji*sgw[DD][c1];

    float sA = aA0 + aA1, qA = aA0*aA0 + aA1*aA1;
    float sB = aB0 + aB1, qB = aB0*aB0 + aB1*aB1;
    #pragma unroll
    for (int o=16; o>=1; o>>=1) {
        sA += __shfl_xor_sync(0xffffffffu, sA, o);
        qA += __shfl_xor_sync(0xffffffffu, qA, o);
        sB += __shfl_xor_sync(0xffffffffu, sB, o);
        qB += __shfl_xor_sync(0xffffffffu, qB, o);
    }
    float mA = sA*(1.f/DD);
    float rA = rsqrtf(fmaf(-mA, mA, qA*(1.f/DD)) + LNEPS);
    float mB = sB*(1.f/DD);
    float rB = rsqrtf(fmaf(-mB, mB, qB*(1.f/DD)) + LNEPS);
    float GA0 = fmaxf((aA0-mA)*rA, 0.f), GA1 = fmaxf((aA1-mA)*rA, 0.f);
    float GB0 = fmaxf((aB0-mB)*rB, 0.f), GB1 = fmaxf((aB1-mB)*rB, 0.f);

    float o0 = GA0*GB0*slw[c0] + GA1*GB1*slw[c1];
    #pragma unroll
    for (int o=16; o>=1; o>>=1) o0 += __shfl_xor_sync(0xffffffffu, o0, o);
    if (lane == 0) out[p] = o0 + lb[0];
}

// ------------------------- launch -------------------------------------------
extern "C" void kernel_launch(void* const* d_in, const int* in_sizes, int n_in,
                              void* d_out, int out_size) {
    const int*   x   = (const int*)d_in[0];
    const int*   ei  = (const int*)d_in[1];
    const int*   pos = (const int*)d_in[2];
    const float* emb = (const float*)d_in[3];
    const float* sWl = (const float*)d_in[4];
    const float* sbl = (const float*)d_in[5];
    const float* sWr = (const float*)d_in[6];
    const float* hW  = (const float*)d_in[7];
    const float* hb  = (const float*)d_in[8];
    const float* gW  = (const float*)d_in[9];
    const float* gb  = (const float*)d_in[10];
    const float* lW  = (const float*)d_in[11];
    const float* lb  = (const float*)d_in[12];
    float* out = (float*)d_out;

    cudaFuncSetAttribute(k_pair, cudaFuncAttributeMaxDynamicSharedMemorySize,
                         (int)sizeof(PairSmem));

    k_init<<<256, 256>>>(x, emb);
    k_scat0<<<NE*32/256, 256>>>(ei);
    k_sage<<<NN, DD>>>(sWl, sbl, sWr, 0);
    k_scatter<<<NE*32/256, 256>>>(ei);
    k_sage<<<NN, DD>>>(sWl, sbl, sWr, 1);
    k_pair<<<272, 256, sizeof(PairSmem)>>>(hW, hb);
    k_prec<<<dim3(NN,2), DD>>>(gW);
    k_gpairs<<<(NP*32)/256, 256>>>(pos, gW, gb, lW, lb, out);
}

// round 16
// speedup vs baseline: 1.1034x; 1.1034x over previous
#include <cuda_runtime.h>
#include <cuda_fp16.h>
#include <cstdint>

#define NN 1024
#define DD 64
#define NE 16384
#define NP 8192
#define LNEPS 1e-5f

// ------------------------- helpers ------------------------------------------
__device__ __forceinline__ uint32_t pack_h2(float x, float y) {
    __half2 h = __floats2half2_rn(x, y);
    return *reinterpret_cast<uint32_t*>(&h);
}
__device__ __forceinline__ uint32_t hmul2u(uint32_t a, uint32_t b) {
    uint32_t r; asm("mul.rn.f16x2 %0,%1,%2;" : "=r"(r) : "r"(a), "r"(b)); return r;
}
__device__ __forceinline__ uint32_t hadd2u(uint32_t a, uint32_t b) {
    uint32_t r; asm("add.rn.f16x2 %0,%1,%2;" : "=r"(r) : "r"(a), "r"(b)); return r;
}
__device__ __forceinline__ float2 h22f2(uint32_t h) {
    __half2 hh = *reinterpret_cast<__half2*>(&h);
    return __half22float2(hh);
}
__device__ __forceinline__ void mma_f16(float* d, uint32_t a0, uint32_t a1,
                                        uint32_t a2, uint32_t a3,
                                        uint32_t b0, uint32_t b1) {
    asm volatile(
        "mma.sync.aligned.m16n8k16.row.col.f32.f16.f16.f32 "
        "{%0,%1,%2,%3}, {%4,%5,%6,%7}, {%8,%9}, {%0,%1,%2,%3};"
        : "+f"(d[0]), "+f"(d[1]), "+f"(d[2]), "+f"(d[3])
        : "r"(a0), "r"(a1), "r"(a2), "r"(a3), "r"(b0), "r"(b1));
}
__device__ __forceinline__ void red2(float* gptr, float x, float y) {
    asm volatile("red.global.add.v2.f32 [%0], {%1,%2};"
                 :: "l"(gptr), "f"(x), "f"(y) : "memory");
}

// ------------------------- scratch (device globals) -------------------------
__device__ float    d_h[NN*DD];
__device__ float    d_hn[NN*DD];
__device__ float    d_aggr[NN*DD];
__device__ float    d_deg[NN];
__device__ unsigned d_bitmap[NN*NN/32];
__device__ float    d_vecp[NN*DD];
__device__ float    d_vecq[NN*DD];
__device__ float    d_VP[NN*DD];
__device__ float    d_VQ[NN*DD];

// ------------------------- phase A ------------------------------------------
__global__ void k_init(const int* __restrict__ x, const float* __restrict__ emb) {
    int t  = blockIdx.x*blockDim.x + threadIdx.x;
    int st = gridDim.x*blockDim.x;
    uint4 z4 = make_uint4(0u,0u,0u,0u);
    float4 zf = make_float4(0.f,0.f,0.f,0.f);
    uint4*  bm4 = reinterpret_cast<uint4*>(d_bitmap);
    float4* vp4 = reinterpret_cast<float4*>(d_vecp);
    float4* vq4 = reinterpret_cast<float4*>(d_vecq);
    float4* ag4 = reinterpret_cast<float4*>(d_aggr);
    for (int i=t; i<NN*NN/128; i+=st) bm4[i] = z4;
    for (int i=t; i<NN;        i+=st) d_deg[i] = 0.f;
    for (int i=t; i<NN*DD/4;   i+=st) { vp4[i]=zf; vq4[i]=zf; ag4[i]=zf; }
    for (int i=t; i<NN*DD;     i+=st) d_h[i] = emb[x[i>>6]*DD + (i&63)];
}

__global__ void k_scat0(const int* __restrict__ ei) {
    int t = blockIdx.x*blockDim.x + threadIdx.x;
    if (t < NE*32) {
        int e = t>>5, cq = t&31;
        int s = ei[e], d = ei[NE+e];
        float2 v = *reinterpret_cast<const float2*>(&d_h[s*DD + cq*2]);
        red2(&d_aggr[d*DD + cq*2], v.x, v.y);
        if (cq == 0) {
            atomicAdd(&d_deg[d], 1.f);
            unsigned idx = (unsigned)s*NN + (unsigned)d;
            atomicOr(&d_bitmap[idx>>5], 1u << (idx & 31u));
        }
    }
}

__global__ void k_scatter(const int* __restrict__ ei) {
    int t = blockIdx.x*blockDim.x + threadIdx.x;
    if (t < NE*32) {
        int e = t>>5, cq = t&31;
        float2 v = *reinterpret_cast<const float2*>(&d_hn[ei[e]*DD + cq*2]);
        red2(&d_aggr[ei[NE+e]*DD + cq*2], v.x, v.y);
    }
}

// 4 nodes per 256-thread block; weights staged in smem once per block.
__global__ void k_sage(const float* __restrict__ Wl, const float* __restrict__ bl,
                       const float* __restrict__ Wr, int layer) {
    __shared__ float swl[DD*DD];
    __shared__ float swr[DD*DD];
    __shared__ float s_in[4][DD], s_ag[4][DD], s_red[4][DD];
    int t = threadIdx.x;
    int gl = t >> 6, c = t & 63;
    int i = blockIdx.x*4 + gl;
    const float* hs = layer ? d_hn : d_h;
    float*       hd = layer ? d_h  : d_hn;
    const float* wl = Wl + layer*DD*DD;
    const float* wr = Wr + layer*DD*DD;
    for (int idx=t; idx<DD*DD; idx+=256) { swl[idx] = wl[idx]; swr[idx] = wr[idx]; }
    float dg = fmaxf(d_deg[i], 1.f);
    s_in[gl][c] = hs[i*DD+c];
    s_ag[gl][c] = d_aggr[i*DD+c] / dg;
    d_aggr[i*DD+c] = 0.f;
    __syncthreads();
    float acc = bl[layer*DD + c];
    #pragma unroll 8
    for (int k=0; k<DD; k++)
        acc = fmaf(s_ag[gl][k], swl[k*DD+c], fmaf(s_in[gl][k], swr[k*DD+c], acc));
    s_red[gl][c] = acc;
    __syncthreads();
    float m = 0.f;
    #pragma unroll 8
    for (int k=0; k<DD; k++) m += s_red[gl][k];
    m *= (1.f/DD);
    float v = 0.f;
    #pragma unroll 8
    for (int k=0; k<DD; k++) { float dd0 = s_red[gl][k]-m; v = fmaf(dd0, dd0, v); }
    v *= (1.f/DD);
    hd[i*DD+c] = (acc - m) * rsqrtf(v + LNEPS);
}

// ------------------------- phase B: mma.sync f16 pair kernel (R13) ----------
struct PairSmem {
    uint32_t hi_h[64][36];     // h rows i-block as half2 along k
    uint32_t hj_h[64][36];
    uint32_t swh[32][68];      // W as half2 packed along k
    float    st[8][16][68];    // warp-private row sums (write-once per i0b)
    float    st2[8][16][68];   // warp-private mirror CORRECTIONS (RMW, sparse)
    float    vqa[64][68];      // vq by jj (normal)
    float    vqa2[64][68];     // vecp corrections by jj (mirror delta)
    float    svp[64][68];      // vp by ii (normal)
    float    svq2[64][68];     // vecq corrections by ii (mirror delta)
    float    hwe[64], hbias[64];
    unsigned bm0[64][2], bm1[64][2];
};

__device__ __forceinline__ void ln16s(const float* pre, float& m, float& r) {
    float s1 = 0.f, s2 = 0.f;
    #pragma unroll
    for (int i=0;i<16;i++) { s1 += pre[i]; s2 = fmaf(pre[i], pre[i], s2); }
    s1 += __shfl_xor_sync(0xffffffffu, s1, 1);
    s2 += __shfl_xor_sync(0xffffffffu, s2, 1);
    s1 += __shfl_xor_sync(0xffffffffu, s1, 2);
    s2 += __shfl_xor_sync(0xffffffffu, s2, 2);
    m = s1 * (1.f/DD);
    r = rsqrtf(fmaf(-m, m, s2*(1.f/DD)) + LNEPS);
}

__device__ __forceinline__ void vq_reduce_acc(const float* vs, float* vqrow,
                                              int g, int tg) {
    uint32_t vh[8];
    #pragma unroll
    for (int i=0;i<8;i++) vh[i] = pack_h2(vs[2*i], vs[2*i+1]);
    #pragma unroll
    for (int msk=4; msk<=16; msk<<=1) {
        #pragma unroll
        for (int i=0;i<8;i++)
            vh[i] = hadd2u(vh[i], __shfl_xor_sync(0xffffffffu, vh[i], msk));
    }
    if (g == 0) {
        #pragma unroll
        for (int nt=0; nt<8; nt++) {
            int ch0 = nt*8 + 2*tg;
            float2 add = h22f2(vh[nt]);
            float2* p = reinterpret_cast<float2*>(&vqrow[ch0]);
            float2 v = *p; v.x += add.x; v.y += add.y; *p = v;
        }
    }
}

__device__ __forceinline__ void emit(float* rs, float* vqrow,
                                     const float* pre0, const float* pre1,
                                     int g, int tg,
                                     float& m0, float& r0, float& m1, float& r1) {
    ln16s(pre0, m0, r0);
    ln16s(pre1, m1, r1);
    float vs[16];
    #pragma unroll
    for (int nt=0; nt<8; nt++) {
        int i0i = 2*nt, i1i = i0i+1;
        float b00 = fmaxf((pre0[i0i]-m0)*r0, 0.f);
        float b01 = fmaxf((pre0[i1i]-m0)*r0, 0.f);
        float b10 = fmaxf((pre1[i0i]-m1)*r1, 0.f);
        float b11 = fmaxf((pre1[i1i]-m1)*r1, 0.f);
        vs[i0i] = b00 + b10; vs[i1i] = b01 + b11;
        rs[i0i]    += b00;  rs[i1i]    += b01;
        rs[16+i0i] += b10;  rs[16+i1i] += b11;
    }
    vq_reduce_acc(vs, vqrow, g, tg);
}

__device__ __forceinline__ void emit_delta(float (*stacc)[68], float* vqrow,
                                           const float* pre0, const float* pre1,
                                           float d0, float d1,
                                           float m0, float r0, float m1, float r1,
                                           const float* we_r, int g, int tg) {
    float pm0[16], pm1[16];
    #pragma unroll
    for (int i=0;i<16;i++) {
        pm0[i] = fmaf(d0, we_r[i], pre0[i]);
        pm1[i] = fmaf(d1, we_r[i], pre1[i]);
    }
    float mm0, rr0, mm1, rr1;
    ln16s(pm0, mm0, rr0);
    ln16s(pm1, mm1, rr1);
    float vs[16];
    #pragma unroll
    for (int nt=0; nt<8; nt++) {
        int i0i = 2*nt, i1i = i0i+1;
        float dl00 = fmaxf((pm0[i0i]-mm0)*rr0,0.f) - fmaxf((pre0[i0i]-m0)*r0,0.f);
        float dl01 = fmaxf((pm0[i1i]-mm0)*rr0,0.f) - fmaxf((pre0[i1i]-m0)*r0,0.f);
        float dl10 = fmaxf((pm1[i0i]-mm1)*rr1,0.f) - fmaxf((pre1[i0i]-m1)*r1,0.f);
        float dl11 = fmaxf((pm1[i1i]-mm1)*rr1,0.f) - fmaxf((pre1[i1i]-m1)*r1,0.f);
        vs[i0i] = dl00 + dl10; vs[i1i] = dl01 + dl11;
        int ch0 = nt*8 + 2*tg;
        float2* pA = reinterpret_cast<float2*>(&stacc[g][ch0]);
        float2 a = *pA; a.x += dl00; a.y += dl01; *pA = a;
        float2* pB = reinterpret_cast<float2*>(&stacc[g+8][ch0]);
        float2 b = *pB; b.x += dl10; b.y += dl11; *pB = b;
    }
    vq_reduce_acc(vs, vqrow, g, tg);
}

__global__ void __launch_bounds__(256,1) k_pair(const float* __restrict__ hW,
                                                const float* __restrict__ hb) {
    extern __shared__ char smraw[];
    PairSmem* sm = reinterpret_cast<PairSmem*>(smraw);
    int t = threadIdx.x;
    int lane = t & 31, w = t >> 5;
    int g = lane >> 2, tg = lane & 3;

    int bi = 0, rem = blockIdx.x;
    while (rem >= 16 - bi) { rem -= 16 - bi; bi++; }
    int bj = bi + rem;
    int i0 = bi*64, j0 = bj*64;
    bool diag = (bi == bj);

    for (int idx=t; idx<DD*32; idx+=256) {
        int r = idx>>5, kp = idx&31;
        sm->hi_h[r][kp] = pack_h2(d_h[(i0+r)*DD + 2*kp], d_h[(i0+r)*DD + 2*kp+1]);
        sm->hj_h[r][kp] = pack_h2(d_h[(j0+r)*DD + 2*kp], d_h[(j0+r)*DD + 2*kp+1]);
        sm->swh[kp][r]  = pack_h2(hW[(2*kp)*DD + r], hW[(2*kp+1)*DD + r]);
    }
    for (int idx=t; idx<DD*68; idx+=256) {
        sm->vqa [idx/68][idx%68] = 0.f;
        sm->vqa2[idx/68][idx%68] = 0.f;
        sm->svp [idx/68][idx%68] = 0.f;
        sm->svq2[idx/68][idx%68] = 0.f;
    }
    if (t < DD) { sm->hwe[t] = hW[DD*DD + t]; sm->hbias[t] = hb[t]; }
    if (t < 128) {
        int r = t>>1, wd = t&1;
        sm->bm0[r][wd] = d_bitmap[((unsigned)(i0+r)*NN + (unsigned)j0)/32 + wd];
        sm->bm1[r][wd] = d_bitmap[((unsigned)(j0+r)*NN + (unsigned)i0)/32 + wd];
    }
    __syncthreads();

    float hb_r[16], we_r[16];
    #pragma unroll
    for (int i=0;i<16;i++) {
        int ch = (i>>1)*8 + 2*tg + (i&1);
        hb_r[i] = sm->hbias[ch];
        we_r[i] = sm->hwe[ch];
    }

    for (int i0b=0; i0b<4; i0b++) {
        int ii0 = i0b*16;
        {
            float4 z = make_float4(0.f,0.f,0.f,0.f);
            float* st2f = &sm->st2[w][0][0];
            for (int idx=lane; idx<16*17; idx+=32)
                *reinterpret_cast<float4*>(st2f + idx*4) = z;
        }
        float rs[32];
        #pragma unroll
        for (int i=0;i<32;i++) rs[i] = 0.f;
        __syncwarp();

        for (int q=0; q<4; q++) {
            int jjA = w*8 + 2*q, jjB = jjA + 1;

            float accA[8][4], accB[8][4];
            #pragma unroll
            for (int nt=0; nt<8; nt++) {
                accA[nt][0]=accA[nt][1]=accA[nt][2]=accA[nt][3]=0.f;
                accB[nt][0]=accB[nt][1]=accB[nt][2]=accB[nt][3]=0.f;
            }

            #pragma unroll
            for (int kt=0; kt<4; kt++) {
                int kp0 = kt*8 + tg, kp1 = kp0 + 4;
                uint32_t hjA0 = sm->hj_h[jjA][kp0], hjA1 = sm->hj_h[jjA][kp1];
                uint32_t hjB0 = sm->hj_h[jjB][kp0], hjB1 = sm->hj_h[jjB][kp1];
                uint32_t hg0  = sm->hi_h[ii0+g][kp0],   hg1  = sm->hi_h[ii0+g][kp1];
                uint32_t h80  = sm->hi_h[ii0+g+8][kp0], h81  = sm->hi_h[ii0+g+8][kp1];

                uint32_t aA0 = hmul2u(hg0, hjA0);
                uint32_t aA1 = hmul2u(h80, hjA0);
                uint32_t aA2 = hmul2u(hg1, hjA1);
                uint32_t aA3 = hmul2u(h81, hjA1);
                uint32_t aB0 = hmul2u(hg0, hjB0);
                uint32_t aB1 = hmul2u(h80, hjB0);
                uint32_t aB2 = hmul2u(hg1, hjB1);
                uint32_t aB3 = hmul2u(h81, hjB1);

                #pragma unroll
                for (int nt=0; nt<8; nt++) {
                    uint32_t b0 = sm->swh[kp0][nt*8 + g];
                    uint32_t b1 = sm->swh[kp1][nt*8 + g];
                    mma_f16(accA[nt], aA0, aA1, aA2, aA3, b0, b1);
                    mma_f16(accB[nt], aB0, aB1, aB2, aB3, b0, b1);
                }
            }

            #pragma unroll
            for (int half=0; half<2; half++) {
                int jj = half ? jjB : jjA;
                float (*acc)[4] = half ? accB : accA;
                float e_g  = ((sm->bm0[ii0+g  ][jj>>5] >> (jj&31)) & 1u) ? 1.f : 0.f;
                float e_g8 = ((sm->bm0[ii0+g+8][jj>>5] >> (jj&31)) & 1u) ? 1.f : 0.f;
                float pre0[16], pre1[16];
                #pragma unroll
                for (int nt=0; nt<8; nt++) {
                    #pragma unroll
                    for (int hf=0; hf<2; hf++) {
                        int i = 2*nt + hf;
                        pre0[i] = acc[nt][hf]   + hb_r[i] + e_g *we_r[i];
                        pre1[i] = acc[nt][2+hf] + hb_r[i] + e_g8*we_r[i];
                    }
                }
                float m0, r0, m1, r1;
                emit(rs, sm->vqa[jj], pre0, pre1, g, tg, m0, r0, m1, r1);

                if (!diag) {
                    float ep_g  = ((sm->bm1[jj][(ii0+g  )>>5] >> ((ii0+g  )&31)) & 1u) ? 1.f : 0.f;
                    float ep_g8 = ((sm->bm1[jj][(ii0+g+8)>>5] >> ((ii0+g+8)&31)) & 1u) ? 1.f : 0.f;
                    float dd0 = ep_g - e_g, dd1 = ep_g8 - e_g8;
                    bool nd = (dd0 != 0.f) || (dd1 != 0.f);
                    if (__any_sync(0xffffffffu, nd)) {
                        emit_delta(sm->st2[w], sm->vqa2[jj], pre0, pre1,
                                   dd0, dd1, m0, r0, m1, r1, we_r, g, tg);
                    }
                }
            }
        }

        // ---- write register row sums to st (once per i0b) ----
        #pragma unroll
        for (int nt=0; nt<8; nt++) {
            int ch0 = nt*8 + 2*tg;
            *reinterpret_cast<float2*>(&sm->st[w][g  ][ch0]) = make_float2(rs[2*nt],    rs[2*nt+1]);
            *reinterpret_cast<float2*>(&sm->st[w][g+8][ch0]) = make_float2(rs[16+2*nt], rs[16+2*nt+1]);
        }

        // ---- block reduce warp-private accumulators (once per ii0 group) ----
        __syncthreads();
        {
            int r = t >> 4, cq = (t & 15) * 4;
            float4 s4 = make_float4(0.f,0.f,0.f,0.f);
            #pragma unroll
            for (int ww=0; ww<8; ww++) {
                float4 v = *reinterpret_cast<float4*>(&sm->st[ww][r][cq]);
                s4.x += v.x; s4.y += v.y; s4.z += v.z; s4.w += v.w;
            }
            float4* d4 = reinterpret_cast<float4*>(&sm->svp[ii0+r][cq]);
            float4 o = *d4;
            o.x += s4.x; o.y += s4.y; o.z += s4.z; o.w += s4.w;
            *d4 = o;
            if (!diag) {
                float4 s5 = make_float4(0.f,0.f,0.f,0.f);
                #pragma unroll
                for (int ww=0; ww<8; ww++) {
                    float4 v = *reinterpret_cast<float4*>(&sm->st2[ww][r][cq]);
                    s5.x += v.x; s5.y += v.y; s5.z += v.z; s5.w += v.w;
                }
                float4* d5 = reinterpret_cast<float4*>(&sm->svq2[ii0+r][cq]);
                float4 o2 = *d5;
                o2.x += s5.x; o2.y += s5.y; o2.z += s5.z; o2.w += s5.w;
                *d5 = o2;
            }
        }
        __syncthreads();
    }

    // ---- flush (vector reductions): mirror = normal + sparse corrections ----
    for (int idx=t; idx<DD*DD/2; idx+=256) {
        int rr = idx>>5, cq = (idx&31)*2;
        float rs0 = sm->svp[rr][cq], rs1 = sm->svp[rr][cq+1];
        float cs0 = sm->vqa[rr][cq], cs1 = sm->vqa[rr][cq+1];
        red2(&d_vecp[(i0+rr)*DD + cq], rs0, rs1);
        red2(&d_vecq[(j0+rr)*DD + cq], cs0, cs1);
        if (!diag) {
            red2(&d_vecq[(i0+rr)*DD + cq], rs0 + sm->svq2[rr][cq], rs1 + sm->svq2[rr][cq+1]);
            red2(&d_vecp[(j0+rr)*DD + cq], cs0 + sm->vqa2[rr][cq], cs1 + sm->vqa2[rr][cq+1]);
        }
    }
}

// ------------------------- phase C ------------------------------------------
// 4 nodes per 256-thread block; gW slice staged in smem once per block.
__global__ void k_prec(const float* __restrict__ gW) {
    __shared__ float sw[DD*DD];
    __shared__ float sv[4][DD];
    int t = threadIdx.x;
    int which = blockIdx.y;
    const float* src  = which ? d_vecq : d_vecp;
    const float* wsrc = gW + (which ? 129 : 65)*DD;
    float*       dst  = which ? d_VQ : d_VP;
    for (int idx=t; idx<DD*DD; idx+=256) sw[idx] = wsrc[idx];
    int gl = t >> 6, c = t & 63;
    int node = blockIdx.x*4 + gl;
    sv[gl][c] = src[node*DD + c];
    __syncthreads();
    float acc = 0.f;
    #pragma unroll 8
    for (int k=0; k<DD; k++) acc = fmaf(sv[gl][k], sw[k*DD+c], acc);
    dst[node*DD + c] = acc;
}

__global__ void k_gpairs(const int* __restrict__ pos, const float* __restrict__ gW,
                         const float* __restrict__ gb, const float* __restrict__ lW,
                         const float* __restrict__ lb, float* __restrict__ out) {
    __shared__ float sgw[DD+1][DD];
    __shared__ float sgb[DD], slw[DD];
    int t = threadIdx.x;
    for (int idx=t; idx<(DD+1)*DD; idx+=256) sgw[idx>>6][idx&63] = gW[idx];
    if (t < DD) { sgb[t] = gb[t]; slw[t] = lW[t]; }
    __syncthreads();

    int gt = blockIdx.x*256 + t;
    int p = gt >> 5, lane = gt & 31;
    if (p >= NP) return;
    int i = pos[2*p], j = pos[2*p+1];
    int c0 = lane, c1 = lane + 32;
    const float* hi = d_h + i*DD;
    const float* hj = d_h + j*DD;

    float g0 = 0.f, g1 = 0.f;
    #pragma unroll 8
    for (int k=0; k<DD; k++) {
        float a = hi[k]*hj[k];
        g0 = fmaf(a, sgw[k][c0], g0);
        g1 = fmaf(a, sgw[k][c1], g1);
    }
    unsigned bij = (unsigned)i*NN + (unsigned)j;
    unsigned bji = (unsigned)j*NN + (unsigned)i;
    float eij = ((d_bitmap[bij>>5] >> (bij & 31u)) & 1u) ? 1.f : 0.f;
    float eji = ((d_bitmap[bji>>5] >> (bji & 31u)) & 1u) ? 1.f : 0.f;

    float aA0 = g0 + sgb[c0] + d_VP[i*DD+c0] + d_VQ[j*DD+c0] + eij*sgw[DD][c0];
    float aA1 = g1 + sgb[c1] + d_VP[i*DD+c1] + d_VQ[j*DD+c1] + eij*sgw[DD][c1];
    float aB0 = g0 + sgb[c0] + d_VP[j*DD+c0] + d_VQ[i*DD+c0] + eji*sgw[DD][c0];
    float aB1 = g1 + sgb[c1] + d_VP[j*DD+c1] + d_VQ[i*DD+c1] + eji*sgw[DD][c1];

    float sA = aA0 + aA1, qA = aA0*aA0 + aA1*aA1;
    float sB = aB0 + aB1, qB = aB0*aB0 + aB1*aB1;
    #pragma unroll
    for (int o=16; o>=1; o>>=1) {
        sA += __shfl_xor_sync(0xffffffffu, sA, o);
        qA += __shfl_xor_sync(0xffffffffu, qA, o);
        sB += __shfl_xor_sync(0xffffffffu, sB, o);
        qB += __shfl_xor_sync(0xffffffffu, qB, o);
    }
    float mA = sA*(1.f/DD);
    float rA = rsqrtf(fmaf(-mA, mA, qA*(1.f/DD)) + LNEPS);
    float mB = sB*(1.f/DD);
    float rB = rsqrtf(fmaf(-mB, mB, qB*(1.f/DD)) + LNEPS);
    float GA0 = fmaxf((aA0-mA)*rA, 0.f), GA1 = fmaxf((aA1-mA)*rA, 0.f);
    float GB0 = fmaxf((aB0-mB)*rB, 0.f), GB1 = fmaxf((aB1-mB)*rB, 0.f);

    float o0 = GA0*GB0*slw[c0] + GA1*GB1*slw[c1];
    #pragma unroll
    for (int o=16; o>=1; o>>=1) o0 += __shfl_xor_sync(0xffffffffu, o0, o);
    if (lane == 0) out[p] = o0 + lb[0];
}

// ------------------------- launch -------------------------------------------
extern "C" void kernel_launch(void* const* d_in, const int* in_sizes, int n_in,
                              void* d_out, int out_size) {
    const int*   x   = (const int*)d_in[0];
    const int*   ei  = (const int*)d_in[1];
    const int*   pos = (const int*)d_in[2];
    const float* emb = (const float*)d_in[3];
    const float* sWl = (const float*)d_in[4];
    const float* sbl = (const float*)d_in[5];
    const float* sWr = (const float*)d_in[6];
    const float* hW  = (const float*)d_in[7];
    const float* hb  = (const float*)d_in[8];
    const float* gW  = (const float*)d_in[9];
    const float* gb  = (const float*)d_in[10];
    const float* lW  = (const float*)d_in[11];
    const float* lb  = (const float*)d_in[12];
    float* out = (float*)d_out;

    cudaFuncSetAttribute(k_pair, cudaFuncAttributeMaxDynamicSharedMemorySize,
                         (int)sizeof(PairSmem));

    k_init<<<512, 256>>>(x, emb);
    k_scat0<<<NE*32/256, 256>>>(ei);
    k_sage<<<NN/4, 256>>>(sWl, sbl, sWr, 0);
    k_scatter<<<NE*32/256, 256>>>(ei);
    k_sage<<<NN/4, 256>>>(sWl, sbl, sWr, 1);
    k_pair<<<136, 256, sizeof(PairSmem)>>>(hW, hb);
    k_prec<<<dim3(NN/4, 2), 256>>>(gW);
    k_gpairs<<<(NP*32)/256, 256>>>(pos, gW, gb, lW, lb, out);
}

// round 17
// speedup vs baseline: 1.1599x; 1.0513x over previous
#include <cuda_runtime.h>
#include <cuda_fp16.h>
#include <cstdint>

#define NN 1024
#define DD 64
#define NE 16384
#define NP 8192
#define LNEPS 1e-5f

// ------------------------- helpers ------------------------------------------
__device__ __forceinline__ uint32_t pack_h2(float x, float y) {
    __half2 h = __floats2half2_rn(x, y);
    return *reinterpret_cast<uint32_t*>(&h);
}
__device__ __forceinline__ uint32_t hmul2u(uint32_t a, uint32_t b) {
    uint32_t r; asm("mul.rn.f16x2 %0,%1,%2;" : "=r"(r) : "r"(a), "r"(b)); return r;
}
__device__ __forceinline__ uint32_t hadd2u(uint32_t a, uint32_t b) {
    uint32_t r; asm("add.rn.f16x2 %0,%1,%2;" : "=r"(r) : "r"(a), "r"(b)); return r;
}
__device__ __forceinline__ float2 h22f2(uint32_t h) {
    __half2 hh = *reinterpret_cast<__half2*>(&h);
    return __half22float2(hh);
}
__device__ __forceinline__ void mma_f16(float* d, uint32_t a0, uint32_t a1,
                                        uint32_t a2, uint32_t a3,
                                        uint32_t b0, uint32_t b1) {
    asm volatile(
        "mma.sync.aligned.m16n8k16.row.col.f32.f16.f16.f32 "
        "{%0,%1,%2,%3}, {%4,%5,%6,%7}, {%8,%9}, {%0,%1,%2,%3};"
        : "+f"(d[0]), "+f"(d[1]), "+f"(d[2]), "+f"(d[3])
        : "r"(a0), "r"(a1), "r"(a2), "r"(a3), "r"(b0), "r"(b1));
}
__device__ __forceinline__ void red2(float* gptr, float x, float y) {
    asm volatile("red.global.add.v2.f32 [%0], {%1,%2};"
                 :: "l"(gptr), "f"(x), "f"(y) : "memory");
}

// ------------------------- scratch (device globals) -------------------------
__device__ float    d_h[NN*DD];
__device__ float    d_hn[NN*DD];
__device__ float    d_aggr[NN*DD];
__device__ float    d_deg[NN];
__device__ unsigned d_bitmap[NN*NN/32];
__device__ float    d_vecp[NN*DD];
__device__ float    d_vecq[NN*DD];
__device__ float    d_VP[NN*DD];
__device__ float    d_VQ[NN*DD];

// ------------------------- phase A ------------------------------------------
__global__ void k_init(const int* __restrict__ x, const float* __restrict__ emb) {
    int t  = blockIdx.x*blockDim.x + threadIdx.x;
    int st = gridDim.x*blockDim.x;
    uint4 z4 = make_uint4(0u,0u,0u,0u);
    float4 zf = make_float4(0.f,0.f,0.f,0.f);
    uint4*  bm4 = reinterpret_cast<uint4*>(d_bitmap);
    float4* vp4 = reinterpret_cast<float4*>(d_vecp);
    float4* vq4 = reinterpret_cast<float4*>(d_vecq);
    float4* ag4 = reinterpret_cast<float4*>(d_aggr);
    for (int i=t; i<NN*NN/128; i+=st) bm4[i] = z4;
    for (int i=t; i<NN;        i+=st) d_deg[i] = 0.f;
    for (int i=t; i<NN*DD/4;   i+=st) { vp4[i]=zf; vq4[i]=zf; ag4[i]=zf; }
    for (int i=t; i<NN*DD;     i+=st) d_h[i] = emb[x[i>>6]*DD + (i&63)];
}

__global__ void k_scat0(const int* __restrict__ ei) {
    int t = blockIdx.x*blockDim.x + threadIdx.x;
    if (t < NE*32) {
        int e = t>>5, cq = t&31;
        int s = ei[e], d = ei[NE+e];
        float2 v = *reinterpret_cast<const float2*>(&d_h[s*DD + cq*2]);
        red2(&d_aggr[d*DD + cq*2], v.x, v.y);
        if (cq == 0) {
            atomicAdd(&d_deg[d], 1.f);
            unsigned idx = (unsigned)s*NN + (unsigned)d;
            atomicOr(&d_bitmap[idx>>5], 1u << (idx & 31u));
        }
    }
}

__global__ void k_scatter(const int* __restrict__ ei) {
    int t = blockIdx.x*blockDim.x + threadIdx.x;
    if (t < NE*32) {
        int e = t>>5, cq = t&31;
        float2 v = *reinterpret_cast<const float2*>(&d_hn[ei[e]*DD + cq*2]);
        red2(&d_aggr[ei[NE+e]*DD + cq*2], v.x, v.y);
    }
}

__global__ void k_sage(const float* __restrict__ Wl, const float* __restrict__ bl,
                       const float* __restrict__ Wr, int layer) {
    __shared__ float s_in[DD], s_ag[DD], s_red[DD];
    int i = blockIdx.x, c = threadIdx.x;
    const float* hs = layer ? d_hn : d_h;
    float*       hd = layer ? d_h  : d_hn;
    float dg = fmaxf(d_deg[i], 1.f);
    s_in[c] = hs[i*DD+c];
    s_ag[c] = d_aggr[i*DD+c] / dg;
    d_aggr[i*DD+c] = 0.f;
    __syncthreads();
    const float* wl = Wl + layer*DD*DD;
    const float* wr = Wr + layer*DD*DD;
    float acc = bl[layer*DD + c];
    #pragma unroll 8
    for (int k=0; k<DD; k++)
        acc = fmaf(s_ag[k], wl[k*DD+c], fmaf(s_in[k], wr[k*DD+c], acc));
    s_red[c] = acc;
    __syncthreads();
    float m = 0.f;
    #pragma unroll 8
    for (int k=0; k<DD; k++) m += s_red[k];
    m *= (1.f/DD);
    float v = 0.f;
    #pragma unroll 8
    for (int k=0; k<DD; k++) { float dd0 = s_red[k]-m; v = fmaf(dd0, dd0, v); }
    v *= (1.f/DD);
    hd[i*DD+c] = (acc - m) * rsqrtf(v + LNEPS);
}

// ------------------------- phase B: mma.sync f16 pair kernel ----------------
struct PairSmem {
    uint32_t hi_h[64][36];     // h rows i-block as half2 along k (stride 36)
    uint32_t hj_h[64][36];
    uint32_t swh[32][68];      // W as half2 packed along k
    float    st[8][16][68];    // warp-private row sums (write-once per i0b)
    float    st2[8][16][68];   // warp-private mirror CORRECTIONS (RMW, sparse)
    float    vqa[64][68];      // vq by jj (normal)
    float    vqa2[64][68];     // vecp corrections by jj (mirror delta)
    float    svp[64][68];      // vp by ii (normal)
    float    svq2[64][68];     // vecq corrections by ii (mirror delta)
    float    hwe[64], hbias[64];
    unsigned bm0[64][2], bm1[64][2];
};

// single-pass LN stats
__device__ __forceinline__ void ln16s(const float* pre, float& m, float& r) {
    float s1 = 0.f, s2 = 0.f;
    #pragma unroll
    for (int i=0;i<16;i++) { s1 += pre[i]; s2 = fmaf(pre[i], pre[i], s2); }
    s1 += __shfl_xor_sync(0xffffffffu, s1, 1);
    s2 += __shfl_xor_sync(0xffffffffu, s2, 1);
    s1 += __shfl_xor_sync(0xffffffffu, s1, 2);
    s2 += __shfl_xor_sync(0xffffffffu, s2, 2);
    m = s1 * (1.f/DD);
    r = rsqrtf(fmaf(-m, m, s2*(1.f/DD)) + LNEPS);
}

// packed 3-level butterfly over g-lanes, then fp32 accumulate @g==0
__device__ __forceinline__ void vq_reduce_acc(const float* vs, float* vqrow,
                                              int g, int tg) {
    uint32_t vh[8];
    #pragma unroll
    for (int i=0;i<8;i++) vh[i] = pack_h2(vs[2*i], vs[2*i+1]);
    #pragma unroll
    for (int msk=4; msk<=16; msk<<=1) {
        #pragma unroll
        for (int i=0;i<8;i++)
            vh[i] = hadd2u(vh[i], __shfl_xor_sync(0xffffffffu, vh[i], msk));
    }
    if (g == 0) {
        #pragma unroll
        for (int nt=0; nt<8; nt++) {
            int ch0 = nt*8 + 2*tg;
            float2 add = h22f2(vh[nt]);
            float2* p = reinterpret_cast<float2*>(&vqrow[ch0]);
            float2 v = *p; v.x += add.x; v.y += add.y; *p = v;
        }
    }
}

// normal emission: row sums into rs registers, col sums via packed butterfly.
__device__ __forceinline__ void emit(float* rs, float* vqrow,
                                     const float* pre0, const float* pre1,
                                     int g, int tg,
                                     float& m0, float& r0, float& m1, float& r1) {
    ln16s(pre0, m0, r0);
    ln16s(pre1, m1, r1);
    float vs[16];
    #pragma unroll
    for (int nt=0; nt<8; nt++) {
        int i0i = 2*nt, i1i = i0i+1;
        float b00 = fmaxf((pre0[i0i]-m0)*r0, 0.f);
        float b01 = fmaxf((pre0[i1i]-m0)*r0, 0.f);
        float b10 = fmaxf((pre1[i0i]-m1)*r1, 0.f);
        float b11 = fmaxf((pre1[i1i]-m1)*r1, 0.f);
        vs[i0i] = b00 + b10; vs[i1i] = b01 + b11;
        rs[i0i]    += b00;  rs[i1i]    += b01;
        rs[16+i0i] += b10;  rs[16+i1i] += b11;
    }
    vq_reduce_acc(vs, vqrow, g, tg);
}

// mirror delta emission: (b_mirror - b_normal) into correction buffers.
__device__ __forceinline__ void emit_delta(float (*stacc)[68], float* vqrow,
                                           const float* pre0, const float* pre1,
                                           float d0, float d1,
                                           float m0, float r0, float m1, float r1,
                                           const float* we_r, int g, int tg) {
    float pm0[16], pm1[16];
    #pragma unroll
    for (int i=0;i<16;i++) {
        pm0[i] = fmaf(d0, we_r[i], pre0[i]);
        pm1[i] = fmaf(d1, we_r[i], pre1[i]);
    }
    float mm0, rr0, mm1, rr1;
    ln16s(pm0, mm0, rr0);
    ln16s(pm1, mm1, rr1);
    float vs[16];
    #pragma unroll
    for (int nt=0; nt<8; nt++) {
        int i0i = 2*nt, i1i = i0i+1;
        float dl00 = fmaxf((pm0[i0i]-mm0)*rr0,0.f) - fmaxf((pre0[i0i]-m0)*r0,0.f);
        float dl01 = fmaxf((pm0[i1i]-mm0)*rr0,0.f) - fmaxf((pre0[i1i]-m0)*r0,0.f);
        float dl10 = fmaxf((pm1[i0i]-mm1)*rr1,0.f) - fmaxf((pre1[i0i]-m1)*r1,0.f);
        float dl11 = fmaxf((pm1[i1i]-mm1)*rr1,0.f) - fmaxf((pre1[i1i]-m1)*r1,0.f);
        vs[i0i] = dl00 + dl10; vs[i1i] = dl01 + dl11;
        int ch0 = nt*8 + 2*tg;
        float2* pA = reinterpret_cast<float2*>(&stacc[g][ch0]);
        float2 a = *pA; a.x += dl00; a.y += dl01; *pA = a;
        float2* pB = reinterpret_cast<float2*>(&stacc[g+8][ch0]);
        float2 b = *pB; b.x += dl10; b.y += dl11; *pB = b;
    }
    vq_reduce_acc(vs, vqrow, g, tg);
}

__global__ void __launch_bounds__(256,1) k_pair(const float* __restrict__ hW,
                                                const float* __restrict__ hb) {
    extern __shared__ char smraw[];
    PairSmem* sm = reinterpret_cast<PairSmem*>(smraw);
    int t = threadIdx.x;
    int lane = t & 31, w = t >> 5;
    int g = lane >> 2, tg = lane & 3;

    int bi = 0, rem = blockIdx.x;
    while (rem >= 16 - bi) { rem -= 16 - bi; bi++; }
    int bj = bi + rem;
    int i0 = bi*64, j0 = bj*64;
    bool diag = (bi == bj);

    for (int idx=t; idx<DD*32; idx+=256) {
        int r = idx>>5, kp = idx&31;
        sm->hi_h[r][kp] = pack_h2(d_h[(i0+r)*DD + 2*kp], d_h[(i0+r)*DD + 2*kp+1]);
        sm->hj_h[r][kp] = pack_h2(d_h[(j0+r)*DD + 2*kp], d_h[(j0+r)*DD + 2*kp+1]);
        sm->swh[kp][r]  = pack_h2(hW[(2*kp)*DD + r], hW[(2*kp+1)*DD + r]);
    }
    for (int idx=t; idx<DD*68; idx+=256) {
        sm->vqa [idx/68][idx%68] = 0.f;
        sm->vqa2[idx/68][idx%68] = 0.f;
        sm->svp [idx/68][idx%68] = 0.f;
        sm->svq2[idx/68][idx%68] = 0.f;
    }
    if (t < DD) { sm->hwe[t] = hW[DD*DD + t]; sm->hbias[t] = hb[t]; }
    if (t < 128) {
        int r = t>>1, wd = t&1;
        sm->bm0[r][wd] = d_bitmap[((unsigned)(i0+r)*NN + (unsigned)j0)/32 + wd];
        sm->bm1[r][wd] = d_bitmap[((unsigned)(j0+r)*NN + (unsigned)i0)/32 + wd];
    }
    __syncthreads();

    float hb_r[16], we_r[16];
    #pragma unroll
    for (int i=0;i<16;i++) {
        int ch = (i>>1)*8 + 2*tg + (i&1);
        hb_r[i] = sm->hbias[ch];
        we_r[i] = sm->hwe[ch];
    }

    for (int i0b=0; i0b<4; i0b++) {
        int ii0 = i0b*16;
        {
            float4 z = make_float4(0.f,0.f,0.f,0.f);
            float* st2f = &sm->st2[w][0][0];
            for (int idx=lane; idx<16*17; idx+=32)
                *reinterpret_cast<float4*>(st2f + idx*4) = z;
        }
        float rs[32];
        #pragma unroll
        for (int i=0;i<32;i++) rs[i] = 0.f;
        __syncwarp();

        for (int q=0; q<4; q++) {
            int jjA = w*8 + 2*q, jjB = jjA + 1;

            float accA[8][4], accB[8][4];
            #pragma unroll
            for (int nt=0; nt<8; nt++) {
                accA[nt][0]=accA[nt][1]=accA[nt][2]=accA[nt][3]=0.f;
                accB[nt][0]=accB[nt][1]=accB[nt][2]=accB[nt][3]=0.f;
            }

            #pragma unroll
            for (int kt=0; kt<4; kt++) {
                int kp0 = kt*8 + tg, kp1 = kp0 + 4;
                uint32_t hjA0 = sm->hj_h[jjA][kp0], hjA1 = sm->hj_h[jjA][kp1];
                uint32_t hjB0 = sm->hj_h[jjB][kp0], hjB1 = sm->hj_h[jjB][kp1];
                uint32_t hg0  = sm->hi_h[ii0+g][kp0],   hg1  = sm->hi_h[ii0+g][kp1];
                uint32_t h80  = sm->hi_h[ii0+g+8][kp0], h81  = sm->hi_h[ii0+g+8][kp1];

                uint32_t aA0 = hmul2u(hg0, hjA0);
                uint32_t aA1 = hmul2u(h80, hjA0);
                uint32_t aA2 = hmul2u(hg1, hjA1);
                uint32_t aA3 = hmul2u(h81, hjA1);
                uint32_t aB0 = hmul2u(hg0, hjB0);
                uint32_t aB1 = hmul2u(h80, hjB0);
                uint32_t aB2 = hmul2u(hg1, hjB1);
                uint32_t aB3 = hmul2u(h81, hjB1);

                #pragma unroll
                for (int nt=0; nt<8; nt++) {
                    uint32_t b0 = sm->swh[kp0][nt*8 + g];
                    uint32_t b1 = sm->swh[kp1][nt*8 + g];
                    mma_f16(accA[nt], aA0, aA1, aA2, aA3, b0, b1);
                    mma_f16(accB[nt], aB0, aB1, aB2, aB3, b0, b1);
                }
            }

            #pragma unroll
            for (int half=0; half<2; half++) {
                int jj = half ? jjB : jjA;
                float (*acc)[4] = half ? accB : accA;
                float e_g  = ((sm->bm0[ii0+g  ][jj>>5] >> (jj&31)) & 1u) ? 1.f : 0.f;
                float e_g8 = ((sm->bm0[ii0+g+8][jj>>5] >> (jj&31)) & 1u) ? 1.f : 0.f;
                float pre0[16], pre1[16];
                #pragma unroll
                for (int nt=0; nt<8; nt++) {
                    #pragma unroll
                    for (int hf=0; hf<2; hf++) {
                        int i = 2*nt + hf;
                        pre0[i] = acc[nt][hf]   + hb_r[i] + e_g *we_r[i];
                        pre1[i] = acc[nt][2+hf] + hb_r[i] + e_g8*we_r[i];
                    }
                }
                float m0, r0, m1, r1;
                emit(rs, sm->vqa[jj], pre0, pre1, g, tg, m0, r0, m1, r1);

                if (!diag) {
                    float ep_g  = ((sm->bm1[jj][(ii0+g  )>>5] >> ((ii0+g  )&31)) & 1u) ? 1.f : 0.f;
                    float ep_g8 = ((sm->bm1[jj][(ii0+g+8)>>5] >> ((ii0+g+8)&31)) & 1u) ? 1.f : 0.f;
                    float dd0 = ep_g - e_g, dd1 = ep_g8 - e_g8;
                    bool nd = (dd0 != 0.f) || (dd1 != 0.f);
                    if (__any_sync(0xffffffffu, nd)) {
                        emit_delta(sm->st2[w], sm->vqa2[jj], pre0, pre1,
                                   dd0, dd1, m0, r0, m1, r1, we_r, g, tg);
                    }
                }
            }
        }

        // ---- write register row sums to st (once per i0b) ----
        #pragma unroll
        for (int nt=0; nt<8; nt++) {
            int ch0 = nt*8 + 2*tg;
            *reinterpret_cast<float2*>(&sm->st[w][g  ][ch0]) = make_float2(rs[2*nt],    rs[2*nt+1]);
            *reinterpret_cast<float2*>(&sm->st[w][g+8][ch0]) = make_float2(rs[16+2*nt], rs[16+2*nt+1]);
        }

        // ---- block reduce warp-private accumulators (once per ii0 group) ----
        __syncthreads();
        {
            int r = t >> 4, cq = (t & 15) * 4;
            float4 s4 = make_float4(0.f,0.f,0.f,0.f);
            #pragma unroll
            for (int ww=0; ww<8; ww++) {
                float4 v = *reinterpret_cast<float4*>(&sm->st[ww][r][cq]);
                s4.x += v.x; s4.y += v.y; s4.z += v.z; s4.w += v.w;
            }
            float4* d4 = reinterpret_cast<float4*>(&sm->svp[ii0+r][cq]);
            float4 o = *d4;
            o.x += s4.x; o.y += s4.y; o.z += s4.z; o.w += s4.w;
            *d4 = o;
            if (!diag) {
                float4 s5 = make_float4(0.f,0.f,0.f,0.f);
                #pragma unroll
                for (int ww=0; ww<8; ww++) {
                    float4 v = *reinterpret_cast<float4*>(&sm->st2[ww][r][cq]);
                    s5.x += v.x; s5.y += v.y; s5.z += v.z; s5.w += v.w;
                }
                float4* d5 = reinterpret_cast<float4*>(&sm->svq2[ii0+r][cq]);
                float4 o2 = *d5;
                o2.x += s5.x; o2.y += s5.y; o2.z += s5.z; o2.w += s5.w;
                *d5 = o2;
            }
        }
        __syncthreads();
    }

    // ---- flush (vector reductions): mirror = normal + sparse corrections ----
    for (int idx=t; idx<DD*DD/2; idx+=256) {
        int rr = idx>>5, cq = (idx&31)*2;
        float rs0 = sm->svp[rr][cq], rs1 = sm->svp[rr][cq+1];
        float cs0 = sm->vqa[rr][cq], cs1 = sm->vqa[rr][cq+1];
        red2(&d_vecp[(i0+rr)*DD + cq], rs0, rs1);
        red2(&d_vecq[(j0+rr)*DD + cq], cs0, cs1);
        if (!diag) {
            red2(&d_vecq[(i0+rr)*DD + cq], rs0 + sm->svq2[rr][cq], rs1 + sm->svq2[rr][cq+1]);
            red2(&d_vecp[(j0+rr)*DD + cq], cs0 + sm->vqa2[rr][cq], cs1 + sm->vqa2[rr][cq+1]);
        }
    }
}

// ------------------------- phase C ------------------------------------------
__global__ void k_prec(const float* __restrict__ gW) {
    __shared__ float s_v[DD];
    int i = blockIdx.x, c = threadIdx.x;
    int which = blockIdx.y;
    const float* src = which ? d_vecq : d_vecp;
    const float* w   = gW + (which ? 129 : 65)*DD;
    float*       dst = which ? d_VQ : d_VP;
    s_v[c] = src[i*DD + c];
    __syncthreads();
    float acc = 0.f;
    #pragma unroll 8
    for (int k=0; k<DD; k++) acc = fmaf(s_v[k], w[k*DD+c], acc);
    dst[i*DD + c] = acc;
}

__global__ void k_gpairs(const int* __restrict__ pos, const float* __restrict__ gW,
                         const float* __restrict__ gb, const float* __restrict__ lW,
                         const float* __restrict__ lb, float* __restrict__ out) {
    __shared__ float sgw[DD+1][DD];
    __shared__ float sgb[DD], slw[DD];
    int t = threadIdx.x;
    for (int idx=t; idx<(DD+1)*DD; idx+=256) sgw[idx>>6][idx&63] = gW[idx];
    if (t < DD) { sgb[t] = gb[t]; slw[t] = lW[t]; }
    __syncthreads();

    int gt = blockIdx.x*256 + t;
    int p = gt >> 5, lane = gt & 31;
    if (p >= NP) return;
    int i = pos[2*p], j = pos[2*p+1];
    int c0 = lane, c1 = lane + 32;
    const float* hi = d_h + i*DD;
    const float* hj = d_h + j*DD;

    float g0 = 0.f, g1 = 0.f;
    #pragma unroll 8
    for (int k=0; k<DD; k++) {
        float a = hi[k]*hj[k];
        g0 = fmaf(a, sgw[k][c0], g0);
        g1 = fmaf(a, sgw[k][c1], g1);
    }
    unsigned bij = (unsigned)i*NN + (unsigned)j;
    unsigned bji = (unsigned)j*NN + (unsigned)i;
    float eij = ((d_bitmap[bij>>5] >> (bij & 31u)) & 1u) ? 1.f : 0.f;
    float eji = ((d_bitmap[bji>>5] >> (bji & 31u)) & 1u) ? 1.f : 0.f;

    float aA0 = g0 + sgb[c0] + d_VP[i*DD+c0] + d_VQ[j*DD+c0] + eij*sgw[DD][c0];
    float aA1 = g1 + sgb[c1] + d_VP[i*DD+c1] + d_VQ[j*DD+c1] + eij*sgw[DD][c1];
    float aB0 = g0 + sgb[c0] + d_VP[j*DD+c0] + d_VQ[i*DD+c0] + eji*sgw[DD][c0];
    float aB1 = g1 + sgb[c1] + d_VP[j*DD+c1] + d_VQ[i*DD+c1] + eji*sgw[DD][c1];

    float sA = aA0 + aA1, qA = aA0*aA0 + aA1*aA1;
    float sB = aB0 + aB1, qB = aB0*aB0 + aB1*aB1;
    #pragma unroll
    for (int o=16; o>=1; o>>=1) {
        sA += __shfl_xor_sync(0xffffffffu, sA, o);
        qA += __shfl_xor_sync(0xffffffffu, qA, o);
        sB += __shfl_xor_sync(0xffffffffu, sB, o);
        qB += __shfl_xor_sync(0xffffffffu, qB, o);
    }
    float mA = sA*(1.f/DD);
    float rA = rsqrtf(fmaf(-mA, mA, qA*(1.f/DD)) + LNEPS);
    float mB = sB*(1.f/DD);
    float rB = rsqrtf(fmaf(-mB, mB, qB*(1.f/DD)) + LNEPS);
    float GA0 = fmaxf((aA0-mA)*rA, 0.f), GA1 = fmaxf((aA1-mA)*rA, 0.f);
    float GB0 = fmaxf((aB0-mB)*rB, 0.f), GB1 = fmaxf((aB1-mB)*rB, 0.f);

    float o0 = GA0*GB0*slw[c0] + GA1*GB1*slw[c1];
    #pragma unroll
    for (int o=16; o>=1; o>>=1) o0 += __shfl_xor_sync(0xffffffffu, o0, o);
    if (lane == 0) out[p] = o0 + lb[0];
}

// ------------------------- launch -------------------------------------------
extern "C" void kernel_launch(void* const* d_in, const int* in_sizes, int n_in,
                              void* d_out, int out_size) {
    const int*   x   = (const int*)d_in[0];
    const int*   ei  = (const int*)d_in[1];
    const int*   pos = (const int*)d_in[2];
    const float* emb = (const float*)d_in[3];
    const float* sWl = (const float*)d_in[4];
    const float* sbl = (const float*)d_in[5];
    const float* sWr = (const float*)d_in[6];
    const float* hW  = (const float*)d_in[7];
    const float* hb  = (const float*)d_in[8];
    const float* gW  = (const float*)d_in[9];
    const float* gb  = (const float*)d_in[10];
    const float* lW  = (const float*)d_in[11];
    const float* lb  = (const float*)d_in[12];
    float* out = (float*)d_out;

    cudaFuncSetAttribute(k_pair, cudaFuncAttributeMaxDynamicSharedMemorySize,
                         (int)sizeof(PairSmem));

    k_init<<<256, 256>>>(x, emb);
    k_scat0<<<NE*32/256, 256>>>(ei);
    k_sage<<<NN, DD>>>(sWl, sbl, sWr, 0);
    k_scatter<<<NE*32/256, 256>>>(ei);
    k_sage<<<NN, DD>>>(sWl, sbl, sWr, 1);
    k_pair<<<136, 256, sizeof(PairSmem)>>>(hW, hb);
    k_prec<<<dim3(NN,2), DD>>>(gW);
    k_gpairs<<<(NP*32)/256, 256>>>(pos, gW, gb, lW, lb, out);
}